// round 7
// baseline (speedup 1.0000x reference)
#include <cuda_runtime.h>
#include <cuda_bf16.h>
#include <math.h>

#define B_TOK 128
#define H_DIM 2048
#define E_NUM 64
#define I_DIM 768
#define TOPK  8
#define NPAIR (B_TOK * TOPK)

// ---------------- scratch (no allocs allowed) ----------------
__device__ float g_topk_w[NPAIR];
__device__ int   g_topk_i[NPAIR];
__device__ int   g_pair_tok[NPAIR];
__device__ int   g_pair_slot[NPAIR];
__device__ float g_pair_w[NPAIR];
__device__ int   g_ofs[E_NUM];
__device__ int   g_cnt[E_NUM];
__device__ float g_inter[(size_t)NPAIR * I_DIM];          // 3 MB
__device__ float g_outp[(size_t)NPAIR * H_DIM];           // 8 MB

// ---------------- gating: logits -> top8 -> renorm weights ----------------
__global__ __launch_bounds__(256) void gate_kernel(const float* __restrict__ x,
                                                   const float* __restrict__ gw) {
    __shared__ float xs[H_DIM];
    __shared__ float logits[E_NUM];
    int b = blockIdx.x;
    for (int i = threadIdx.x; i < H_DIM; i += 256) xs[i] = x[(size_t)b * H_DIM + i];
    __syncthreads();
    int warp = threadIdx.x >> 5, lane = threadIdx.x & 31;
    for (int e = warp; e < E_NUM; e += 8) {
        const float* w = gw + (size_t)e * H_DIM;
        float s = 0.f;
        for (int h = lane; h < H_DIM; h += 32) s += xs[h] * w[h];
        #pragma unroll
        for (int o = 16; o; o >>= 1) s += __shfl_xor_sync(0xffffffffu, s, o);
        if (lane == 0) logits[e] = s;
    }
    __syncthreads();
    if (threadIdx.x == 0) {
        float lv[E_NUM];
        for (int e = 0; e < E_NUM; e++) lv[e] = logits[e];
        int   sel[TOPK];
        float selv[TOPK];
        for (int k = 0; k < TOPK; k++) {
            int   bi = -1;
            float bv = -1e30f;
            for (int e = 0; e < E_NUM; e++) {
                if (lv[e] > bv) { bv = lv[e]; bi = e; }
            }
            sel[k] = bi; selv[k] = bv; lv[bi] = -1e30f;
        }
        float mx = selv[0];
        float sum = 0.f;
        float wv[TOPK];
        for (int k = 0; k < TOPK; k++) { wv[k] = expf(selv[k] - mx); sum += wv[k]; }
        float inv = 1.f / sum;
        for (int k = 0; k < TOPK; k++) {
            g_topk_i[b * TOPK + k] = sel[k];
            g_topk_w[b * TOPK + k] = wv[k] * inv;
        }
    }
}

// ---------------- deterministic counting sort of pairs by expert ----------------
__global__ __launch_bounds__(1024) void build_lists_kernel() {
    __shared__ int sidx[NPAIR];
    __shared__ int scnt[E_NUM];
    __shared__ int sofs[E_NUM];
    int t = threadIdx.x;  // 0..1023 = pair id (b*8+k)
    sidx[t] = g_topk_i[t];
    if (t < E_NUM) scnt[t] = 0;
    __syncthreads();
    atomicAdd(&scnt[sidx[t]], 1);
    __syncthreads();
    if (t == 0) {
        int a = 0;
        for (int e = 0; e < E_NUM; e++) { sofs[e] = a; a += scnt[e]; }
    }
    __syncthreads();
    int e = sidx[t];
    int r = 0;
    for (int q = 0; q < t; q++) r += (sidx[q] == e) ? 1 : 0;  // stable rank
    int pos = sofs[e] + r;
    g_pair_tok[pos]  = t >> 3;
    g_pair_slot[pos] = t;
    g_pair_w[pos]    = g_topk_w[t];
    if (t < E_NUM) { g_ofs[t] = sofs[t]; g_cnt[t] = scnt[t]; }
}

// ---------------- GEMM1 + SiLU: inter[pair, i] ----------------
// grid (6, 64): x = i-block (128 i each), y = expert. 256 threads.
// thread tile: 2 i x 4 tokens, on both gate and up rows. K-chunks of 32.
__global__ __launch_bounds__(256) void gemm1_kernel(const float* __restrict__ x,
                                                    const float* __restrict__ w1) {
    constexpr int IB = 128, TT = 16, HK = 32, S = 33;
    __shared__ float wg[IB][S];
    __shared__ float wu[IB][S];
    __shared__ float xsm[TT][S];

    int e = blockIdx.y;
    int T = g_cnt[e];
    if (T == 0) return;
    int base = g_ofs[e];
    int i0 = blockIdx.x * IB;
    const float* W = w1 + (size_t)e * (2 * I_DIM) * H_DIM;
    int tid = threadIdx.x;
    int tg = tid & 3;        // token group (4 tokens)
    int ig = tid >> 2;       // 0..63 -> i = 2*ig + {0,1}

    for (int t0 = 0; t0 < T; t0 += TT) {
        float ag[2][4], au[2][4];
        #pragma unroll
        for (int a = 0; a < 2; a++)
            #pragma unroll
            for (int b2 = 0; b2 < 4; b2++) { ag[a][b2] = 0.f; au[a][b2] = 0.f; }

        for (int hc = 0; hc < H_DIM; hc += HK) {
            __syncthreads();
            // stage gate + up weight tiles: 128 rows x 32 cols each
            #pragma unroll
            for (int p = 0; p < 4; p++) {
                int f = tid + p * 256;       // float4 id 0..1023
                int r = f >> 3;
                int c = (f & 7) << 2;
                float4 vg = *(const float4*)(W + (size_t)(i0 + r) * H_DIM + hc + c);
                wg[r][c] = vg.x; wg[r][c + 1] = vg.y; wg[r][c + 2] = vg.z; wg[r][c + 3] = vg.w;
                float4 vu = *(const float4*)(W + (size_t)(I_DIM + i0 + r) * H_DIM + hc + c);
                wu[r][c] = vu.x; wu[r][c + 1] = vu.y; wu[r][c + 2] = vu.z; wu[r][c + 3] = vu.w;
            }
            // stage x tokens: 16 x 32
            if (tid < 128) {
                int r = tid >> 3;
                int c = (tid & 7) << 2;
                float4 v = make_float4(0.f, 0.f, 0.f, 0.f);
                int tl = t0 + r;
                if (tl < T) {
                    int tok = g_pair_tok[base + tl];
                    v = *(const float4*)(x + (size_t)tok * H_DIM + hc + c);
                }
                xsm[r][c] = v.x; xsm[r][c + 1] = v.y; xsm[r][c + 2] = v.z; xsm[r][c + 3] = v.w;
            }
            __syncthreads();
            #pragma unroll
            for (int kk = 0; kk < HK; kk++) {
                float xv[4];
                #pragma unroll
                for (int j = 0; j < 4; j++) xv[j] = xsm[4 * tg + j][kk];
                #pragma unroll
                for (int ji = 0; ji < 2; ji++) {
                    float gv = wg[2 * ig + ji][kk];
                    float uv = wu[2 * ig + ji][kk];
                    #pragma unroll
                    for (int j = 0; j < 4; j++) {
                        ag[ji][j] += gv * xv[j];
                        au[ji][j] += uv * xv[j];
                    }
                }
            }
        }
        __syncthreads();
        // epilogue: silu(gate)*up
        #pragma unroll
        for (int jt = 0; jt < 4; jt++) {
            int tl = t0 + 4 * tg + jt;
            if (tl < T) {
                size_t pr = (size_t)(base + tl) * I_DIM;
                #pragma unroll
                for (int ji = 0; ji < 2; ji++) {
                    float g = ag[ji][jt];
                    float u = au[ji][jt];
                    float s = g / (1.f + __expf(-g));
                    g_inter[pr + i0 + 2 * ig + ji] = s * u;
                }
            }
        }
    }
}

// ---------------- GEMM2: out_pair[slot, h] = (inter . w2[e,h,:]) * route_w ----------------
// grid (8, 64): x = h-block (256 rows), y = expert. 256 threads.
// thread tile: 4 rows x 4 tokens. K-chunks of 32 over I=768.
__global__ __launch_bounds__(256) void gemm2_kernel(const float* __restrict__ w2) {
    constexpr int RB = 256, TT = 16, HK = 32, S = 33;
    __shared__ float ws[RB][S];
    __shared__ float xsm[TT][S];

    int e = blockIdx.y;
    int T = g_cnt[e];
    if (T == 0) return;
    int base = g_ofs[e];
    int r0 = blockIdx.x * RB;
    const float* W = w2 + (size_t)e * H_DIM * I_DIM;
    int tid = threadIdx.x;
    int tg = tid & 3;
    int rg = tid >> 2;  // 0..63 -> rows 4*rg..4*rg+3

    for (int t0 = 0; t0 < T; t0 += TT) {
        float acc[4][4];
        #pragma unroll
        for (int a = 0; a < 4; a++)
            #pragma unroll
            for (int b2 = 0; b2 < 4; b2++) acc[a][b2] = 0.f;

        for (int ic = 0; ic < I_DIM; ic += HK) {
            __syncthreads();
            // stage weight tile: 256 rows x 32
            #pragma unroll
            for (int p = 0; p < 8; p++) {
                int f = tid + p * 256;
                int r = f >> 3;
                int c = (f & 7) << 2;
                float4 v = *(const float4*)(W + (size_t)(r0 + r) * I_DIM + ic + c);
                ws[r][c] = v.x; ws[r][c + 1] = v.y; ws[r][c + 2] = v.z; ws[r][c + 3] = v.w;
            }
            // stage inter tile: 16 x 32
            if (tid < 128) {
                int r = tid >> 3;
                int c = (tid & 7) << 2;
                float4 v = make_float4(0.f, 0.f, 0.f, 0.f);
                int tl = t0 + r;
                if (tl < T) v = *(const float4*)(g_inter + (size_t)(base + tl) * I_DIM + ic + c);
                xsm[r][c] = v.x; xsm[r][c + 1] = v.y; xsm[r][c + 2] = v.z; xsm[r][c + 3] = v.w;
            }
            __syncthreads();
            #pragma unroll
            for (int kk = 0; kk < HK; kk++) {
                float xv[4];
                #pragma unroll
                for (int j = 0; j < 4; j++) xv[j] = xsm[4 * tg + j][kk];
                float wv[4];
                #pragma unroll
                for (int j = 0; j < 4; j++) wv[j] = ws[4 * rg + j][kk];
                #pragma unroll
                for (int jr = 0; jr < 4; jr++)
                    #pragma unroll
                    for (int jt = 0; jt < 4; jt++)
                        acc[jr][jt] += wv[jr] * xv[jt];
            }
        }
        __syncthreads();
        #pragma unroll
        for (int jt = 0; jt < 4; jt++) {
            int tl = t0 + 4 * tg + jt;
            if (tl < T) {
                int   slot = g_pair_slot[base + tl];
                float rw   = g_pair_w[base + tl];
                size_t o = (size_t)slot * H_DIM + r0 + 4 * rg;
                g_outp[o + 0] = acc[0][jt] * rw;
                g_outp[o + 1] = acc[1][jt] * rw;
                g_outp[o + 2] = acc[2][jt] * rw;
                g_outp[o + 3] = acc[3][jt] * rw;
            }
        }
    }
}

// ---------------- combine: out[b,h] = sum_k outp[b*8+k, h] ----------------
__global__ __launch_bounds__(256) void combine_kernel(float* __restrict__ out) {
    int g = blockIdx.x * blockDim.x + threadIdx.x;
    int stride = gridDim.x * blockDim.x;
    for (int idx = g; idx < B_TOK * H_DIM; idx += stride) {
        int b = idx >> 11;        // /2048
        int h = idx & (H_DIM - 1);
        float s = 0.f;
        #pragma unroll
        for (int k = 0; k < TOPK; k++)
            s += g_outp[(size_t)(b * TOPK + k) * H_DIM + h];
        out[idx] = s;
    }
}

extern "C" void kernel_launch(void* const* d_in, const int* in_sizes, int n_in,
                              void* d_out, int out_size) {
    const float* x  = (const float*)d_in[0];   // (128, 2048)
    const float* gw = (const float*)d_in[1];   // (64, 2048)
    const float* w1 = (const float*)d_in[2];   // (64, 1536, 2048)
    const float* w2 = (const float*)d_in[3];   // (64, 2048, 768)
    float* out = (float*)d_out;                // (128, 1, 2048)

    gate_kernel<<<B_TOK, 256>>>(x, gw);
    build_lists_kernel<<<1, 1024>>>();
    gemm1_kernel<<<dim3(I_DIM / 128, E_NUM), 256>>>(x, w1);
    gemm2_kernel<<<dim3(H_DIM / 256, E_NUM), 256>>>(w2);
    combine_kernel<<<512, 256>>>(out);
}